// round 1
// baseline (speedup 1.0000x reference)
#include <cuda_runtime.h>
#include <math.h>
#include <float.h>

// ---------------------------------------------------------------------------
// MLA prefill, fp32 baseline.
// B=2, S=2048, HIDDEN=2048, H=16, Q_LORA=768, KV_LORA=512, NOPE=128, ROPE=64,
// QK_HEAD=192, V_DIM=128.  Outputs: attn_output (B,S,2048) then attn_weights
// (B,H,S,S), both fp32, concatenated in d_out.
// ---------------------------------------------------------------------------

#define S_LEN   2048
#define BATCH   2
#define NHEADS  16

// Scratch (device globals: no allocations allowed)
__device__ float g_qa[4096 * 768];                 // hs @ wq_a^T  (then rmsnormed)
__device__ float g_q[(long long)4096 * 3072];      // q projection (B*S, H*192)
__device__ float g_kvfull[4096 * 576];             // hs @ wkv_a^T
__device__ float g_kv_ext[4096 * 576];             // [rmsnorm(kv_lat) | rope(k_pe)]
__device__ float g_q_ext[(long long)32 * 2048 * 576]; // per (b,h): [q_lat | rope(q_pe)]
__device__ float g_ctx[(long long)32 * 2048 * 512];   // attention context
__device__ float g_out[(long long)4096 * 2048];    // pre-wo output

// ---------------------------------------------------------------------------
// Generic batched tiled SGEMM: C = alpha * A * op(B)
//   BT=true : B is (N,K) row-major  -> C = A @ B^T
//   BT=false: B is (K,N) row-major  -> C = A @ B
// Tile 128x128x8, 256 threads, 8x8 per-thread microtile.
// Per-z offsets: z -> (zo=z/zdiv, zi=z%zdiv), ptr += zo*s?o + zi*s?i.
// CAUSAL: skip blocks entirely above the diagonal (C rows=s, cols=t).
// KLIMIT: k loop stops at m0+128 (valid when A[:, t>s] == 0).
// Assumes M % 128 == 0, K % 8 == 0, all leading dims % 4 == 0 (true here).
// N boundary (N=576 case) is guarded.
// ---------------------------------------------------------------------------
template<bool BT, bool CAUSAL, bool KLIMIT>
__global__ __launch_bounds__(256) void gemm_k(
    int M, int N, int K,
    const float* __restrict__ A, int lda, long long sAo, long long sAi,
    const float* __restrict__ B, int ldb, long long sBo, long long sBi,
    float* __restrict__ C, int ldc, long long sCo, long long sCi,
    int zdiv, float alpha)
{
    const int z  = blockIdx.z;
    const int zo = z / zdiv, zi = z % zdiv;
    A += zo * sAo + (long long)zi * sAi;
    B += zo * sBo + (long long)zi * sBi;
    C += zo * sCo + (long long)zi * sCi;

    const int m0 = blockIdx.y * 128;
    const int n0 = blockIdx.x * 128;
    if (CAUSAL && n0 > m0 + 127) return;   // fully masked block
    const int kend = KLIMIT ? min(K, m0 + 128) : K;

    __shared__ float As[8][128];
    __shared__ float Bs[8][128];

    const int tid = threadIdx.x;
    const int ar  = tid >> 1;          // 0..127
    const int ac  = (tid & 1) << 2;    // 0 or 4
    const int br  = tid >> 5;          // 0..7   (normal-mode B)
    const int bc  = (tid & 31) << 2;   // 0..124
    const int tx  = (tid & 15) << 3;   // col base of microtile
    const int ty  = (tid >> 4) << 3;   // row base of microtile

    float acc[8][8];
#pragma unroll
    for (int i = 0; i < 8; i++)
#pragma unroll
        for (int j = 0; j < 8; j++) acc[i][j] = 0.f;

    for (int k0 = 0; k0 < kend; k0 += 8) {
        float4 av = *reinterpret_cast<const float4*>(
            &A[(long long)(m0 + ar) * lda + k0 + ac]);
        As[ac + 0][ar] = av.x; As[ac + 1][ar] = av.y;
        As[ac + 2][ar] = av.z; As[ac + 3][ar] = av.w;

        if (BT) {
            const int n = n0 + ar;
            float4 bv = make_float4(0.f, 0.f, 0.f, 0.f);
            if (n < N)
                bv = *reinterpret_cast<const float4*>(
                    &B[(long long)n * ldb + k0 + ac]);
            Bs[ac + 0][ar] = bv.x; Bs[ac + 1][ar] = bv.y;
            Bs[ac + 2][ar] = bv.z; Bs[ac + 3][ar] = bv.w;
        } else {
            float4 bv = *reinterpret_cast<const float4*>(
                &B[(long long)(k0 + br) * ldb + n0 + bc]);
            *reinterpret_cast<float4*>(&Bs[br][bc]) = bv;
        }
        __syncthreads();

#pragma unroll
        for (int k = 0; k < 8; k++) {
            float a0[8], b0[8];
            float4 t;
            t = *reinterpret_cast<const float4*>(&As[k][ty]);
            a0[0] = t.x; a0[1] = t.y; a0[2] = t.z; a0[3] = t.w;
            t = *reinterpret_cast<const float4*>(&As[k][ty + 4]);
            a0[4] = t.x; a0[5] = t.y; a0[6] = t.z; a0[7] = t.w;
            t = *reinterpret_cast<const float4*>(&Bs[k][tx]);
            b0[0] = t.x; b0[1] = t.y; b0[2] = t.z; b0[3] = t.w;
            t = *reinterpret_cast<const float4*>(&Bs[k][tx + 4]);
            b0[4] = t.x; b0[5] = t.y; b0[6] = t.z; b0[7] = t.w;
#pragma unroll
            for (int i = 0; i < 8; i++)
#pragma unroll
                for (int j = 0; j < 8; j++)
                    acc[i][j] = fmaf(a0[i], b0[j], acc[i][j]);
        }
        __syncthreads();
    }

#pragma unroll
    for (int i = 0; i < 8; i++) {
        const long long m = m0 + ty + i;
#pragma unroll
        for (int j = 0; j < 8; j++) {
            const int n = n0 + tx + j;
            if (n < N) C[m * ldc + n] = alpha * acc[i][j];
        }
    }
}

// ---------------------------------------------------------------------------
// Row RMSNorm: y[row, 0:dim] = x[row, 0:dim] * rsqrt(mean(x^2)+eps) * w
// ---------------------------------------------------------------------------
__global__ __launch_bounds__(256) void rmsnorm_k(
    const float* __restrict__ x, int ldx,
    const float* __restrict__ w,
    float* __restrict__ y, int ldy, int dim)
{
    const long long row = blockIdx.x;
    x += row * ldx; y += row * ldy;
    float s = 0.f;
    for (int i = threadIdx.x; i < dim; i += 256) { float v = x[i]; s += v * v; }
    __shared__ float red[8];
    for (int o = 16; o; o >>= 1) s += __shfl_xor_sync(0xffffffffu, s, o);
    if ((threadIdx.x & 31) == 0) red[threadIdx.x >> 5] = s;
    __syncthreads();
    if (threadIdx.x < 8) {
        float v = red[threadIdx.x];
        for (int o = 4; o; o >>= 1) v += __shfl_xor_sync(0xffu, v, o);
        if (threadIdx.x == 0) red[0] = v;
    }
    __syncthreads();
    const float r = rsqrtf(red[0] / (float)dim + 1e-6f);
    for (int i = threadIdx.x; i < dim; i += 256) y[i] = x[i] * r * w[i];
}

// ---------------------------------------------------------------------------
// RoPE (rotate_half form, head dim 64, halves of 32).
// ---------------------------------------------------------------------------
__global__ void rope_q_k(const float* __restrict__ q,
                         const float* __restrict__ cosb,
                         const float* __restrict__ sinb,
                         float* __restrict__ q_ext)
{
    const int bs = blockIdx.x;            // b*S + s
    const int h  = blockIdx.y;
    const int i  = threadIdx.x;           // 0..63
    const int b  = bs >> 11;
    const int s  = bs & 2047;
    const float* x = q + (long long)bs * 3072 + h * 192 + 128;
    const float c  = cosb[(long long)bs * 64 + i];
    const float sn = sinb[(long long)bs * 64 + i];
    const float xr = (i < 32) ? -x[i + 32] : x[i - 32];
    q_ext[((long long)(b * 16 + h) * 2048 + s) * 576 + 512 + i] = x[i] * c + xr * sn;
}

__global__ void rope_k_k(const float* __restrict__ kvfull,
                         const float* __restrict__ cosb,
                         const float* __restrict__ sinb,
                         float* __restrict__ kv_ext)
{
    const int bs = blockIdx.x;
    const int i  = threadIdx.x;
    const float* x = kvfull + (long long)bs * 576 + 512;
    const float c  = cosb[(long long)bs * 64 + i];
    const float sn = sinb[(long long)bs * 64 + i];
    const float xr = (i < 32) ? -x[i + 32] : x[i - 32];
    kv_ext[(long long)bs * 576 + 512 + i] = x[i] * c + xr * sn;
}

// ---------------------------------------------------------------------------
// Causal in-place softmax over rows of the (B*H*S, S) score matrix.
// Reads only t<=s (rest is garbage/unwritten), writes full row (zeros above
// diagonal). 256 threads, 8 elems/thread in registers.
// ---------------------------------------------------------------------------
__global__ __launch_bounds__(256) void softmax_k(float* __restrict__ P)
{
    const long long row = blockIdx.x;     // (b*H + h)*S + s
    const int s = (int)(row & (S_LEN - 1));
    float* p = P + row * S_LEN;
    const int tid = threadIdx.x;

    float v[8];
    float mx = -FLT_MAX;
#pragma unroll
    for (int i = 0; i < 8; i++) {
        const int t = tid + i * 256;
        v[i] = (t <= s) ? p[t] : -FLT_MAX;
        mx = fmaxf(mx, v[i]);
    }
    __shared__ float red[8];
    for (int o = 16; o; o >>= 1) mx = fmaxf(mx, __shfl_xor_sync(0xffffffffu, mx, o));
    if ((tid & 31) == 0) red[tid >> 5] = mx;
    __syncthreads();
    if (tid < 8) {
        float m2 = red[tid];
        for (int o = 4; o; o >>= 1) m2 = fmaxf(m2, __shfl_xor_sync(0xffu, m2, o));
        if (tid == 0) red[0] = m2;
    }
    __syncthreads();
    mx = red[0];
    __syncthreads();

    float sum = 0.f;
#pragma unroll
    for (int i = 0; i < 8; i++) {
        const int t = tid + i * 256;
        v[i] = (t <= s) ? expf(v[i] - mx) : 0.f;
        sum += v[i];
    }
    for (int o = 16; o; o >>= 1) sum += __shfl_xor_sync(0xffffffffu, sum, o);
    if ((tid & 31) == 0) red[tid >> 5] = sum;
    __syncthreads();
    if (tid < 8) {
        float s2 = red[tid];
        for (int o = 4; o; o >>= 1) s2 += __shfl_xor_sync(0xffu, s2, o);
        if (tid == 0) red[0] = s2;
    }
    __syncthreads();
    const float inv = 1.f / red[0];
#pragma unroll
    for (int i = 0; i < 8; i++) p[tid + i * 256] = v[i] * inv;
}

// ---------------------------------------------------------------------------
extern "C" void kernel_launch(void* const* d_in, const int* in_sizes, int n_in,
                              void* d_out, int out_size)
{
    const float* hs    = (const float*)d_in[0];   // (B,S,2048)
    const float* cosb  = (const float*)d_in[1];   // (B,S,64)
    const float* sinb  = (const float*)d_in[2];   // (B,S,64)
    /* d_in[3] = attention_mask (causal; implemented directly) */
    const float* wq_a  = (const float*)d_in[4];   // (768,2048)
    const float* qnw   = (const float*)d_in[5];   // (768,)
    const float* wq_b  = (const float*)d_in[6];   // (3072,768)
    const float* wkv_a = (const float*)d_in[7];   // (576,2048)
    const float* kvnw  = (const float*)d_in[8];   // (512,)
    const float* wkv_b = (const float*)d_in[9];   // (4096,512)
    const float* wo    = (const float*)d_in[10];  // (2048,2048)

    float* outp = (float*)d_out;                              // (B,S,2048)
    float* attn = outp + (long long)BATCH * S_LEN * 2048;     // (B,H,S,S)

    float *qa, *q, *kvf, *kve, *qe, *ctx, *obuf;
    cudaGetSymbolAddress((void**)&qa,   g_qa);
    cudaGetSymbolAddress((void**)&q,    g_q);
    cudaGetSymbolAddress((void**)&kvf,  g_kvfull);
    cudaGetSymbolAddress((void**)&kve,  g_kv_ext);
    cudaGetSymbolAddress((void**)&qe,   g_q_ext);
    cudaGetSymbolAddress((void**)&ctx,  g_ctx);
    cudaGetSymbolAddress((void**)&obuf, g_out);

    const float scaling = 1.f / sqrtf(192.f);
    const long long SS  = (long long)S_LEN * S_LEN;

    // 1. q_a = hs @ wq_a^T                       (4096 x 768, K=2048)
    gemm_k<true, false, false><<<dim3(6, 32, 1), 256>>>(
        4096, 768, 2048, hs, 2048, 0, 0, wq_a, 2048, 0, 0,
        qa, 768, 0, 0, 1, 1.f);
    // 2. rmsnorm(q_a) in place
    rmsnorm_k<<<4096, 256>>>(qa, 768, qnw, qa, 768, 768);
    // 3. q = q_a @ wq_b^T                        (4096 x 3072, K=768)
    gemm_k<true, false, false><<<dim3(24, 32, 1), 256>>>(
        4096, 3072, 768, qa, 768, 0, 0, wq_b, 768, 0, 0,
        q, 3072, 0, 0, 1, 1.f);
    // 4. kv_full = hs @ wkv_a^T                  (4096 x 576, K=2048)
    gemm_k<true, false, false><<<dim3(5, 32, 1), 256>>>(
        4096, 576, 2048, hs, 2048, 0, 0, wkv_a, 2048, 0, 0,
        kvf, 576, 0, 0, 1, 1.f);
    // 5. kv_ext[:, :512] = rmsnorm(kv_full[:, :512])
    rmsnorm_k<<<4096, 256>>>(kvf, 576, kvnw, kve, 576, 512);
    // 6. kv_ext[:, 512:] = rope(k_pe)
    rope_k_k<<<4096, 64>>>(kvf, cosb, sinb, kve);
    // 7. q_ext[b,h,s, 512:] = rope(q_pe)
    rope_q_k<<<dim3(4096, 16), 64>>>(q, cosb, sinb, qe);
    // 8. q_ext[b,h,s, :512] = q_nope @ wkv_b_h[:, :128]   (per (b,h): 2048x512, K=128)
    gemm_k<false, false, false><<<dim3(4, 16, 32), 256>>>(
        2048, 512, 128,
        q, 3072, (long long)2048 * 3072, 192,
        wkv_b, 512, 0, (long long)256 * 512,
        qe, 576, (long long)16 * 2048 * 576, (long long)2048 * 576,
        16, 1.f);
    // 9. scores = scaling * q_ext @ kv_ext^T  (causal block skip), into d_out
    gemm_k<true, true, false><<<dim3(16, 16, 32), 256>>>(
        2048, 2048, 576,
        qe, 576, (long long)16 * 2048 * 576, (long long)2048 * 576,
        kve, 576, (long long)2048 * 576, 0,
        attn, 2048, 16 * SS, SS,
        16, scaling);
    // 10. in-place causal softmax (writes zeros above diagonal)
    softmax_k<<<BATCH * NHEADS * S_LEN, 256>>>(attn);
    // 11. ctx = P @ kv  (K-limit: P is zero above diagonal)  (2048x512, K=2048)
    gemm_k<false, false, true><<<dim3(4, 16, 32), 256>>>(
        2048, 512, 2048,
        attn, 2048, 16 * SS, SS,
        kve, 576, (long long)2048 * 576, 0,
        ctx, 512, (long long)16 * 2048 * 512, (long long)2048 * 512,
        16, 1.f);
    // 12. out[b,s,h*128+d] = ctx @ wkv_b_h[:,128:]^T   (per (b,h): 2048x128, K=512)
    gemm_k<true, false, false><<<dim3(1, 16, 32), 256>>>(
        2048, 128, 512,
        ctx, 512, (long long)16 * 2048 * 512, (long long)2048 * 512,
        wkv_b + 128 * 512, 512, 0, (long long)256 * 512,
        obuf, 2048, (long long)2048 * 2048, 128,
        16, 1.f);
    // 13. attn_output = out @ wo^T               (4096 x 2048, K=2048)
    gemm_k<true, false, false><<<dim3(16, 32, 1), 256>>>(
        4096, 2048, 2048, obuf, 2048, 0, 0, wo, 2048, 0, 0,
        outp, 2048, 0, 0, 1, 1.f);
}

// round 5
// speedup vs baseline: 2.8196x; 2.8196x over previous
#include <cuda_runtime.h>
#include <math.h>
#include <float.h>
#include <stdint.h>

// ---------------------------------------------------------------------------
// MLA prefill. B=2, S=2048, HIDDEN=2048, H=16, Q_LORA=768, KV_LORA=512,
// NOPE=128, ROPE=64, QK_HEAD=192, V_DIM=128.
// Outputs: attn_output (B,S,2048) then attn_weights (B,H,S,S), fp32.
// GEMMs via mma.sync m16n8k8 tf32. No cp.async, no dynamic smem, no
// tcgen05 — the harness ptxas target (sm_103 base) rejects those.
// ---------------------------------------------------------------------------

#define S_LEN   2048
#define BATCH   2
#define NHEADS  16

// Scratch (device globals: no allocations allowed)
__device__ float g_qa[4096 * 768];
__device__ float g_q[(long long)4096 * 3072];
__device__ float g_kvfull[4096 * 576];
__device__ float g_kv_ext[4096 * 576];
__device__ float g_q_ext[(long long)32 * 2048 * 576];
__device__ float g_ctx[(long long)32 * 2048 * 512];
__device__ float g_out[(long long)4096 * 2048];
__device__ float g_wbT[16 * 512 * 128];            // transposed wkv_b nope slice
__device__ float g_kvT[(long long)2 * 512 * 2048]; // transposed kv latent

__device__ __forceinline__ uint32_t f2tf(float x) {
    uint32_t r;
    asm("cvt.rna.tf32.f32 %0, %1;" : "=r"(r) : "f"(x));
    return r;
}

__device__ __forceinline__ void mma_tf32(float* c, const uint32_t* a,
                                         const uint32_t* b) {
    asm volatile(
        "mma.sync.aligned.m16n8k8.row.col.f32.tf32.tf32.f32 "
        "{%0,%1,%2,%3}, {%4,%5,%6,%7}, {%8,%9}, {%0,%1,%2,%3};"
        : "+f"(c[0]), "+f"(c[1]), "+f"(c[2]), "+f"(c[3])
        : "r"(a[0]), "r"(a[1]), "r"(a[2]), "r"(a[3]), "r"(b[0]), "r"(b[1]));
}

#define SM_STRIDE 20   // 16 + 4 padding (uint32 words); row = 80B, float4-ok

// ---------------------------------------------------------------------------
// mma.sync tf32 GEMM:  C = alpha * A @ B^T
//   A (M,K) row-major, B (N,K) row-major.  CTA 128x128, warp 64x32,
//   K-chunk 16, register-prefetch double buffer, tf32 conversion at staging.
//   CAUSAL: skip blocks fully above diagonal.  KLIMIT: k stops at m0+128.
//   M % 128 == 0, K % 16 == 0; N boundary handled (zero-fill + guarded store).
// ---------------------------------------------------------------------------
template<bool CAUSAL, bool KLIMIT>
__global__ __launch_bounds__(256, 2) void gemm_mma(
    int M, int N, int K,
    const float* __restrict__ A, int lda, long long sAo, long long sAi,
    const float* __restrict__ B, int ldb, long long sBo, long long sBi,
    float* __restrict__ C, int ldc, long long sCo, long long sCi,
    int zdiv, float alpha)
{
    const int m0 = blockIdx.y * 128;
    const int n0 = blockIdx.x * 128;
    if (CAUSAL && n0 > m0 + 127) return;

    __shared__ uint32_t As[2][128 * SM_STRIDE];
    __shared__ uint32_t Bs[2][128 * SM_STRIDE];

    const int z = blockIdx.z;
    const int zo = z / zdiv, zi = z % zdiv;
    A += zo * sAo + (long long)zi * sAi;
    B += zo * sBo + (long long)zi * sBi;
    C += zo * sCo + (long long)zi * sCi;

    const int kend = KLIMIT ? min(K, m0 + 128) : K;
    const int nkt = kend >> 4;

    const int tid  = threadIdx.x;
    const int lane = tid & 31;
    const int wid  = tid >> 5;
    const int wm   = wid & 1;          // warp row (0..1)  -> 64 rows
    const int wn   = wid >> 1;         // warp col (0..3)  -> 32 cols
    const int lr   = lane >> 2;        // 0..7
    const int lc   = lane & 3;         // 0..3

    const int row = tid >> 2;          // 0..63
    const int q   = tid & 3;           // float4 index within 16 floats

    float4 ra[2], rb[2];
    auto gload = [&](int kt) {
        const int k0 = kt << 4;
#pragma unroll
        for (int i = 0; i < 2; i++) {
            const int r = i * 64 + row;
            ra[i] = *reinterpret_cast<const float4*>(
                &A[(long long)(m0 + r) * lda + k0 + q * 4]);
            const int n = n0 + r;
            rb[i] = (n < N)
                ? *reinterpret_cast<const float4*>(
                      &B[(long long)n * ldb + k0 + q * 4])
                : make_float4(0.f, 0.f, 0.f, 0.f);
        }
    };
    auto sstore = [&](int s) {
#pragma unroll
        for (int i = 0; i < 2; i++) {
            const int r = i * 64 + row;
            uint4 a = make_uint4(f2tf(ra[i].x), f2tf(ra[i].y),
                                 f2tf(ra[i].z), f2tf(ra[i].w));
            uint4 b = make_uint4(f2tf(rb[i].x), f2tf(rb[i].y),
                                 f2tf(rb[i].z), f2tf(rb[i].w));
            *reinterpret_cast<uint4*>(&As[s][r * SM_STRIDE + q * 4]) = a;
            *reinterpret_cast<uint4*>(&Bs[s][r * SM_STRIDE + q * 4]) = b;
        }
    };

    float acc[4][4][4];
#pragma unroll
    for (int i = 0; i < 4; i++)
#pragma unroll
        for (int j = 0; j < 4; j++)
#pragma unroll
            for (int r = 0; r < 4; r++) acc[i][j][r] = 0.f;

    gload(0);
    sstore(0);
    __syncthreads();

    for (int kt = 0; kt < nkt; kt++) {
        if (kt + 1 < nkt) gload(kt + 1);   // overlap global latency w/ compute

        const uint32_t* as = As[kt & 1];
        const uint32_t* bs = Bs[kt & 1];
#pragma unroll
        for (int kk = 0; kk < 16; kk += 8) {
            uint32_t bf[4][2];
#pragma unroll
            for (int nf = 0; nf < 4; nf++) {
                const int n = wn * 32 + nf * 8 + lr;
                bf[nf][0] = bs[n * SM_STRIDE + kk + lc];
                bf[nf][1] = bs[n * SM_STRIDE + kk + lc + 4];
            }
#pragma unroll
            for (int mf = 0; mf < 4; mf++) {
                const int r = wm * 64 + mf * 16 + lr;
                uint32_t af[4];
                af[0] = as[r * SM_STRIDE + kk + lc];
                af[1] = as[(r + 8) * SM_STRIDE + kk + lc];
                af[2] = as[r * SM_STRIDE + kk + lc + 4];
                af[3] = as[(r + 8) * SM_STRIDE + kk + lc + 4];
#pragma unroll
                for (int nf = 0; nf < 4; nf++)
                    mma_tf32(acc[mf][nf], af, bf[nf]);
            }
        }
        __syncthreads();
        if (kt + 1 < nkt) {
            sstore((kt + 1) & 1);
            __syncthreads();
        }
    }

    // Epilogue: direct global stores (float2 pairs), alpha applied.
#pragma unroll
    for (int mf = 0; mf < 4; mf++) {
        const int r = m0 + wm * 64 + mf * 16 + lr;
#pragma unroll
        for (int nf = 0; nf < 4; nf++) {
            const int cn = n0 + wn * 32 + nf * 8 + 2 * lc;
            if (cn < N) {
                float2 v0 = make_float2(alpha * acc[mf][nf][0],
                                        alpha * acc[mf][nf][1]);
                float2 v1 = make_float2(alpha * acc[mf][nf][2],
                                        alpha * acc[mf][nf][3]);
                *reinterpret_cast<float2*>(C + (long long)r * ldc + cn) = v0;
                *reinterpret_cast<float2*>(C + (long long)(r + 8) * ldc + cn) = v1;
            }
        }
    }
}

// ---------------------------------------------------------------------------
// RMSNorm
// ---------------------------------------------------------------------------
__global__ __launch_bounds__(256) void rmsnorm_k(
    const float* __restrict__ x, int ldx, const float* __restrict__ w,
    float* __restrict__ y, int ldy, int dim)
{
    const long long row = blockIdx.x;
    x += row * ldx; y += row * ldy;
    float s = 0.f;
    for (int i = threadIdx.x; i < dim; i += 256) { float v = x[i]; s += v * v; }
    __shared__ float red[8];
    for (int o = 16; o; o >>= 1) s += __shfl_xor_sync(0xffffffffu, s, o);
    if ((threadIdx.x & 31) == 0) red[threadIdx.x >> 5] = s;
    __syncthreads();
    if (threadIdx.x < 8) {
        float v = red[threadIdx.x];
        for (int o = 4; o; o >>= 1) v += __shfl_xor_sync(0xffu, v, o);
        if (threadIdx.x == 0) red[0] = v;
    }
    __syncthreads();
    const float r = rsqrtf(red[0] / (float)dim + 1e-6f);
    for (int i = threadIdx.x; i < dim; i += 256) y[i] = x[i] * r * w[i];
}

// ---------------------------------------------------------------------------
// RoPE
// ---------------------------------------------------------------------------
__global__ void rope_q_k(const float* __restrict__ q,
                         const float* __restrict__ cosb,
                         const float* __restrict__ sinb,
                         float* __restrict__ q_ext)
{
    const int bs = blockIdx.x, h = blockIdx.y, i = threadIdx.x;
    const int b = bs >> 11, s = bs & 2047;
    const float* x = q + (long long)bs * 3072 + h * 192 + 128;
    const float c  = cosb[(long long)bs * 64 + i];
    const float sn = sinb[(long long)bs * 64 + i];
    const float xr = (i < 32) ? -x[i + 32] : x[i - 32];
    q_ext[((long long)(b * 16 + h) * 2048 + s) * 576 + 512 + i] = x[i] * c + xr * sn;
}

__global__ void rope_k_k(const float* __restrict__ kvfull,
                         const float* __restrict__ cosb,
                         const float* __restrict__ sinb,
                         float* __restrict__ kv_ext)
{
    const int bs = blockIdx.x, i = threadIdx.x;
    const float* x = kvfull + (long long)bs * 576 + 512;
    const float c  = cosb[(long long)bs * 64 + i];
    const float sn = sinb[(long long)bs * 64 + i];
    const float xr = (i < 32) ? -x[i + 32] : x[i - 32];
    kv_ext[(long long)bs * 576 + 512 + i] = x[i] * c + xr * sn;
}

// ---------------------------------------------------------------------------
// Transpose: out[r][c] = in[c][r]   (r < R, c < Cc), z-batched
// ---------------------------------------------------------------------------
__global__ void transpose_k(const float* __restrict__ in, int ldin, long long sInz,
                            float* __restrict__ out, int ldout, long long sOutz,
                            int R, int Cc)
{
    __shared__ float t[32][33];
    in += blockIdx.z * sInz; out += blockIdx.z * sOutz;
    const int r0 = blockIdx.y * 32, c0 = blockIdx.x * 32;
    const int tx = threadIdx.x, ty = threadIdx.y;
#pragma unroll
    for (int i = 0; i < 32; i += 8) {
        const int c = c0 + ty + i, r = r0 + tx;
        if (c < Cc && r < R) t[ty + i][tx] = in[(long long)c * ldin + r];
    }
    __syncthreads();
#pragma unroll
    for (int i = 0; i < 32; i += 8) {
        const int r = r0 + ty + i, c = c0 + tx;
        if (r < R && c < Cc) out[(long long)r * ldout + c] = t[tx][ty + i];
    }
}

// ---------------------------------------------------------------------------
// Causal in-place softmax
// ---------------------------------------------------------------------------
__global__ __launch_bounds__(256) void softmax_k(float* __restrict__ P)
{
    const long long row = blockIdx.x;
    const int s = (int)(row & (S_LEN - 1));
    float* p = P + row * S_LEN;
    const int tid = threadIdx.x;

    float v[8];
    float mx = -FLT_MAX;
#pragma unroll
    for (int i = 0; i < 8; i++) {
        const int t = tid + i * 256;
        v[i] = (t <= s) ? p[t] : -FLT_MAX;
        mx = fmaxf(mx, v[i]);
    }
    __shared__ float red[8];
    for (int o = 16; o; o >>= 1) mx = fmaxf(mx, __shfl_xor_sync(0xffffffffu, mx, o));
    if ((tid & 31) == 0) red[tid >> 5] = mx;
    __syncthreads();
    if (tid < 8) {
        float m2 = red[tid];
        for (int o = 4; o; o >>= 1) m2 = fmaxf(m2, __shfl_xor_sync(0xffu, m2, o));
        if (tid == 0) red[0] = m2;
    }
    __syncthreads();
    mx = red[0];
    __syncthreads();

    float sum = 0.f;
#pragma unroll
    for (int i = 0; i < 8; i++) {
        const int t = tid + i * 256;
        v[i] = (t <= s) ? expf(v[i] - mx) : 0.f;
        sum += v[i];
    }
    for (int o = 16; o; o >>= 1) sum += __shfl_xor_sync(0xffffffffu, sum, o);
    if ((tid & 31) == 0) red[tid >> 5] = sum;
    __syncthreads();
    if (tid < 8) {
        float s2 = red[tid];
        for (int o = 4; o; o >>= 1) s2 += __shfl_xor_sync(0xffu, s2, o);
        if (tid == 0) red[0] = s2;
    }
    __syncthreads();
    const float inv = 1.f / red[0];
#pragma unroll
    for (int i = 0; i < 8; i++) p[tid + i * 256] = v[i] * inv;
}

// ---------------------------------------------------------------------------
extern "C" void kernel_launch(void* const* d_in, const int* in_sizes, int n_in,
                              void* d_out, int out_size)
{
    const float* hs    = (const float*)d_in[0];
    const float* cosb  = (const float*)d_in[1];
    const float* sinb  = (const float*)d_in[2];
    const float* wq_a  = (const float*)d_in[4];
    const float* qnw   = (const float*)d_in[5];
    const float* wq_b  = (const float*)d_in[6];
    const float* wkv_a = (const float*)d_in[7];
    const float* kvnw  = (const float*)d_in[8];
    const float* wkv_b = (const float*)d_in[9];
    const float* wo    = (const float*)d_in[10];

    float* outp = (float*)d_out;
    float* attn = outp + (long long)BATCH * S_LEN * 2048;

    float *qa, *q, *kvf, *kve, *qe, *ctx, *obuf, *wbT, *kvT;
    cudaGetSymbolAddress((void**)&qa,   g_qa);
    cudaGetSymbolAddress((void**)&q,    g_q);
    cudaGetSymbolAddress((void**)&kvf,  g_kvfull);
    cudaGetSymbolAddress((void**)&kve,  g_kv_ext);
    cudaGetSymbolAddress((void**)&qe,   g_q_ext);
    cudaGetSymbolAddress((void**)&ctx,  g_ctx);
    cudaGetSymbolAddress((void**)&obuf, g_out);
    cudaGetSymbolAddress((void**)&wbT,  g_wbT);
    cudaGetSymbolAddress((void**)&kvT,  g_kvT);

    const float scaling = 1.f / sqrtf(192.f);
    const long long SS  = (long long)S_LEN * S_LEN;

    // 1. qa = hs @ wq_a^T               (4096 x 768, K=2048)
    gemm_mma<false, false><<<dim3(6, 32, 1), 256>>>(
        4096, 768, 2048, hs, 2048, 0, 0, wq_a, 2048, 0, 0,
        qa, 768, 0, 0, 1, 1.f);
    // 2. rmsnorm(qa)
    rmsnorm_k<<<4096, 256>>>(qa, 768, qnw, qa, 768, 768);
    // 3. q = qa @ wq_b^T                (4096 x 3072, K=768)
    gemm_mma<false, false><<<dim3(24, 32, 1), 256>>>(
        4096, 3072, 768, qa, 768, 0, 0, wq_b, 768, 0, 0,
        q, 3072, 0, 0, 1, 1.f);
    // 4. kvf = hs @ wkv_a^T             (4096 x 576, K=2048)
    gemm_mma<false, false><<<dim3(5, 32, 1), 256>>>(
        4096, 576, 2048, hs, 2048, 0, 0, wkv_a, 2048, 0, 0,
        kvf, 576, 0, 0, 1, 1.f);
    // 5-7. rmsnorm + rope
    rmsnorm_k<<<4096, 256>>>(kvf, 576, kvnw, kve, 576, 512);
    rope_k_k<<<4096, 64>>>(kvf, cosb, sinb, kve);
    rope_q_k<<<dim3(4096, 16), 64>>>(q, cosb, sinb, qe);
    // 7b. wbT[h] (512x128) = wkv_b_h[:128,:]^T
    transpose_k<<<dim3(4, 16, 16), dim3(32, 8)>>>(
        wkv_b, 512, (long long)256 * 512, wbT, 128, (long long)512 * 128,
        512, 128);
    // 8. q_ext[:, :512] = q_nope @ wbT^T  (per (b,h): 2048x512, K=128)
    gemm_mma<false, false><<<dim3(4, 16, 32), 256>>>(
        2048, 512, 128,
        q, 3072, (long long)2048 * 3072, 192,
        wbT, 128, 0, (long long)512 * 128,
        qe, 576, (long long)16 * 2048 * 576, (long long)2048 * 576,
        16, 1.f);
    // 9. scores = scaling * q_ext @ kv_ext^T (causal) -> d_out attn region
    gemm_mma<true, false><<<dim3(16, 16, 32), 256>>>(
        2048, 2048, 576,
        qe, 576, (long long)16 * 2048 * 576, (long long)2048 * 576,
        kve, 576, (long long)2048 * 576, 0,
        attn, 2048, 16 * SS, SS,
        16, scaling);
    // 10. causal softmax (in place, writes zeros above diagonal)
    softmax_k<<<BATCH * NHEADS * S_LEN, 256>>>(attn);
    // 10b. kvT[b] (512x2048) = kv_lat^T
    transpose_k<<<dim3(64, 16, 2), dim3(32, 8)>>>(
        kve, 576, (long long)2048 * 576, kvT, 2048, (long long)512 * 2048,
        512, 2048);
    // 11. ctx = P @ kvT^T  (K-limit)    (2048x512, K=2048)
    gemm_mma<false, true><<<dim3(4, 16, 32), 256>>>(
        2048, 512, 2048,
        attn, 2048, 16 * SS, SS,
        kvT, 2048, (long long)512 * 2048, 0,
        ctx, 512, (long long)16 * 2048 * 512, (long long)2048 * 512,
        16, 1.f);
    // 12. out = ctx @ wkv_b_h[:,128:]^T (per (b,h): 2048x128, K=512)
    gemm_mma<false, false><<<dim3(1, 16, 32), 256>>>(
        2048, 128, 512,
        ctx, 512, (long long)16 * 2048 * 512, (long long)2048 * 512,
        wkv_b + 128 * 512, 512, 0, (long long)256 * 512,
        obuf, 2048, (long long)2048 * 2048, 128,
        16, 1.f);
    // 13. attn_output = out @ wo^T      (4096 x 2048, K=2048)
    gemm_mma<false, false><<<dim3(16, 32, 1), 256>>>(
        4096, 2048, 2048, obuf, 2048, 0, 0, wo, 2048, 0, 0,
        outp, 2048, 0, 0, 1, 1.f);
}

// round 9
// speedup vs baseline: 2.9439x; 1.0441x over previous
#include <cuda_runtime.h>
#include <math.h>
#include <float.h>
#include <stdint.h>

// ---------------------------------------------------------------------------
// MLA prefill. B=2, S=2048, HIDDEN=2048, H=16, Q_LORA=768, KV_LORA=512,
// NOPE=128, ROPE=64, QK_HEAD=192, V_DIM=128.
// Outputs: attn_output (B,S,2048) then attn_weights (B,H,S,S), fp32.
// GEMMs via mma.sync m16n8k8 tf32. No cp.async, no dynamic smem, no
// tcgen05 — the harness ptxas target (sm_103 base) rejects those.
// ONE __syncthreads per K-chunk.
// ---------------------------------------------------------------------------

#define S_LEN   2048
#define BATCH   2
#define NHEADS  16

// Scratch (device globals: no allocations allowed)
__device__ float g_qa[4096 * 768];
__device__ float g_q[(long long)4096 * 3072];
__device__ float g_kvfull[4096 * 576];
__device__ float g_kv_ext[4096 * 576];
__device__ float g_q_ext[(long long)32 * 2048 * 576];
__device__ float g_ctx[(long long)32 * 2048 * 512];
__device__ float g_out[(long long)4096 * 2048];
__device__ float g_wbT[16 * 512 * 128];            // transposed wkv_b nope slice
__device__ float g_kvT[(long long)2 * 512 * 2048]; // transposed kv latent

__device__ __forceinline__ uint32_t f2tf(float x) {
    uint32_t r;
    asm("cvt.rna.tf32.f32 %0, %1;" : "=r"(r) : "f"(x));
    return r;
}

__device__ __forceinline__ void mma_tf32(float* c, const uint32_t* a,
                                         const uint32_t* b) {
    asm volatile(
        "mma.sync.aligned.m16n8k8.row.col.f32.tf32.tf32.f32 "
        "{%0,%1,%2,%3}, {%4,%5,%6,%7}, {%8,%9}, {%0,%1,%2,%3};"
        : "+f"(c[0]), "+f"(c[1]), "+f"(c[2]), "+f"(c[3])
        : "r"(a[0]), "r"(a[1]), "r"(a[2]), "r"(a[3]), "r"(b[0]), "r"(b[1]));
}

#define SM_STRIDE 20   // 16 + 4 padding (uint32 words); row = 80B, float4-ok

// ---------------------------------------------------------------------------
// mma.sync tf32 GEMM:  C = alpha * A @ B^T
//   A (M,K) row-major, B (N,K) row-major.  CTA 128x128, warp 64x32,
//   K-chunk 16, register-prefetch double buffer, tf32 conversion at staging,
//   ONE __syncthreads per chunk.
//   CAUSAL: skip blocks fully above diagonal.  KLIMIT: k stops at m0+128.
//   M % 128 == 0, K % 16 == 0; N boundary handled (zero-fill + guarded store).
// ---------------------------------------------------------------------------
template<bool CAUSAL, bool KLIMIT>
__global__ __launch_bounds__(256, 2) void gemm_mma(
    int M, int N, int K,
    const float* __restrict__ A, int lda, long long sAo, long long sAi,
    const float* __restrict__ B, int ldb, long long sBo, long long sBi,
    float* __restrict__ C, int ldc, long long sCo, long long sCi,
    int zdiv, float alpha)
{
    const int m0 = blockIdx.y * 128;
    const int n0 = blockIdx.x * 128;
    if (CAUSAL && n0 > m0 + 127) return;

    __shared__ uint32_t As[2][128 * SM_STRIDE];
    __shared__ uint32_t Bs[2][128 * SM_STRIDE];

    const int z = blockIdx.z;
    const int zo = z / zdiv, zi = z % zdiv;
    A += zo * sAo + (long long)zi * sAi;
    B += zo * sBo + (long long)zi * sBi;
    C += zo * sCo + (long long)zi * sCi;

    const int kend = KLIMIT ? min(K, m0 + 128) : K;
    const int nkt = kend >> 4;

    const int tid  = threadIdx.x;
    const int lane = tid & 31;
    const int wid  = tid >> 5;
    const int wm   = wid & 1;          // warp row (0..1)  -> 64 rows
    const int wn   = wid >> 1;         // warp col (0..3)  -> 32 cols
    const int lr   = lane >> 2;        // 0..7
    const int lc   = lane & 3;         // 0..3

    const int row = tid >> 2;          // 0..63
    const int q   = tid & 3;           // float4 index within 16 floats

    float4 ra[2], rb[2];
    auto gload = [&](int kt) {
        const int k0 = kt << 4;
#pragma unroll
        for (int i = 0; i < 2; i++) {
            const int r = i * 64 + row;
            ra[i] = *reinterpret_cast<const float4*>(
                &A[(long long)(m0 + r) * lda + k0 + q * 4]);
            const int n = n0 + r;
            rb[i] = (n < N)
                ? *reinterpret_cast<const float4*>(
                      &B[(long long)n * ldb + k0 + q * 4])
                : make_float4(0.f, 0.f, 0.f, 0.f);
        }
    };
    auto sstore = [&](int s) {
#pragma unroll
        for (int i = 0; i < 2; i++) {
            const int r = i * 64 + row;
            uint4 a = make_uint4(f2tf(ra[i].x), f2tf(ra[i].y),
                                 f2tf(ra[i].z), f2tf(ra[i].w));
            uint4 b = make_uint4(f2tf(rb[i].x), f2tf(rb[i].y),
                                 f2tf(rb[i].z), f2tf(rb[i].w));
            *reinterpret_cast<uint4*>(&As[s][r * SM_STRIDE + q * 4]) = a;
            *reinterpret_cast<uint4*>(&Bs[s][r * SM_STRIDE + q * 4]) = b;
        }
    };

    float acc[4][4][4];
#pragma unroll
    for (int i = 0; i < 4; i++)
#pragma unroll
        for (int j = 0; j < 4; j++)
#pragma unroll
            for (int r = 0; r < 4; r++) acc[i][j][r] = 0.f;

    gload(0);
    sstore(0);
    __syncthreads();

    for (int kt = 0; kt < nkt; kt++) {
        if (kt + 1 < nkt) gload(kt + 1);   // prefetch next chunk into registers

        const uint32_t* as = As[kt & 1];
        const uint32_t* bs = Bs[kt & 1];
#pragma unroll
        for (int kk = 0; kk < 16; kk += 8) {
            uint32_t bf[4][2];
#pragma unroll
            for (int nf = 0; nf < 4; nf++) {
                const int n = wn * 32 + nf * 8 + lr;
                bf[nf][0] = bs[n * SM_STRIDE + kk + lc];
                bf[nf][1] = bs[n * SM_STRIDE + kk + lc + 4];
            }
#pragma unroll
            for (int mf = 0; mf < 4; mf++) {
                const int r = wm * 64 + mf * 16 + lr;
                uint32_t af[4];
                af[0] = as[r * SM_STRIDE + kk + lc];
                af[1] = as[(r + 8) * SM_STRIDE + kk + lc];
                af[2] = as[r * SM_STRIDE + kk + lc + 4];
                af[3] = as[(r + 8) * SM_STRIDE + kk + lc + 4];
#pragma unroll
                for (int nf = 0; nf < 4; nf++)
                    mma_tf32(acc[mf][nf], af, bf[nf]);
            }
        }
        // Store next chunk into the OTHER buffer (its previous readers finished
        // before the barrier that ended iteration kt-1), then one barrier.
        if (kt + 1 < nkt) sstore((kt + 1) & 1);
        __syncthreads();
    }

    // Epilogue: direct global stores (float2 pairs), alpha applied.
#pragma unroll
    for (int mf = 0; mf < 4; mf++) {
        const int r = m0 + wm * 64 + mf * 16 + lr;
#pragma unroll
        for (int nf = 0; nf < 4; nf++) {
            const int cn = n0 + wn * 32 + nf * 8 + 2 * lc;
            if (cn < N) {
                float2 v0 = make_float2(alpha * acc[mf][nf][0],
                                        alpha * acc[mf][nf][1]);
                float2 v1 = make_float2(alpha * acc[mf][nf][2],
                                        alpha * acc[mf][nf][3]);
                *reinterpret_cast<float2*>(C + (long long)r * ldc + cn) = v0;
                *reinterpret_cast<float2*>(C + (long long)(r + 8) * ldc + cn) = v1;
            }
        }
    }
}

// ---------------------------------------------------------------------------
// RMSNorm
// ---------------------------------------------------------------------------
__global__ __launch_bounds__(256) void rmsnorm_k(
    const float* __restrict__ x, int ldx, const float* __restrict__ w,
    float* __restrict__ y, int ldy, int dim)
{
    const long long row = blockIdx.x;
    x += row * ldx; y += row * ldy;
    float s = 0.f;
    for (int i = threadIdx.x; i < dim; i += 256) { float v = x[i]; s += v * v; }
    __shared__ float red[8];
    for (int o = 16; o; o >>= 1) s += __shfl_xor_sync(0xffffffffu, s, o);
    if ((threadIdx.x & 31) == 0) red[threadIdx.x >> 5] = s;
    __syncthreads();
    if (threadIdx.x < 8) {
        float v = red[threadIdx.x];
        for (int o = 4; o; o >>= 1) v += __shfl_xor_sync(0xffu, v, o);
        if (threadIdx.x == 0) red[0] = v;
    }
    __syncthreads();
    const float r = rsqrtf(red[0] / (float)dim + 1e-6f);
    for (int i = threadIdx.x; i < dim; i += 256) y[i] = x[i] * r * w[i];
}

// ---------------------------------------------------------------------------
// RoPE
// ---------------------------------------------------------------------------
__global__ void rope_q_k(const float* __restrict__ q,
                         const float* __restrict__ cosb,
                         const float* __restrict__ sinb,
                         float* __restrict__ q_ext)
{
    const int bs = blockIdx.x, h = blockIdx.y, i = threadIdx.x;
    const int b = bs >> 11, s = bs & 2047;
    const float* x = q + (long long)bs * 3072 + h * 192 + 128;
    const float c  = cosb[(long long)bs * 64 + i];
    const float sn = sinb[(long long)bs * 64 + i];
    const float xr = (i < 32) ? -x[i + 32] : x[i - 32];
    q_ext[((long long)(b * 16 + h) * 2048 + s) * 576 + 512 + i] = x[i] * c + xr * sn;
}

__global__ void rope_k_k(const float* __restrict__ kvfull,
                         const float* __restrict__ cosb,
                         const float* __restrict__ sinb,
                         float* __restrict__ kv_ext)
{
    const int bs = blockIdx.x, i = threadIdx.x;
    const float* x = kvfull + (long long)bs * 576 + 512;
    const float c  = cosb[(long long)bs * 64 + i];
    const float sn = sinb[(long long)bs * 64 + i];
    const float xr = (i < 32) ? -x[i + 32] : x[i - 32];
    kv_ext[(long long)bs * 576 + 512 + i] = x[i] * c + xr * sn;
}

// ---------------------------------------------------------------------------
// Transpose: out[r][c] = in[c][r]   (r < R, c < Cc), z-batched
// ---------------------------------------------------------------------------
__global__ void transpose_k(const float* __restrict__ in, int ldin, long long sInz,
                            float* __restrict__ out, int ldout, long long sOutz,
                            int R, int Cc)
{
    __shared__ float t[32][33];
    in += blockIdx.z * sInz; out += blockIdx.z * sOutz;
    const int r0 = blockIdx.y * 32, c0 = blockIdx.x * 32;
    const int tx = threadIdx.x, ty = threadIdx.y;
#pragma unroll
    for (int i = 0; i < 32; i += 8) {
        const int c = c0 + ty + i, r = r0 + tx;
        if (c < Cc && r < R) t[ty + i][tx] = in[(long long)c * ldin + r];
    }
    __syncthreads();
#pragma unroll
    for (int i = 0; i < 32; i += 8) {
        const int r = r0 + ty + i, c = c0 + tx;
        if (r < R && c < Cc) out[(long long)r * ldout + c] = t[tx][ty + i];
    }
}

// ---------------------------------------------------------------------------
// Causal in-place softmax
// ---------------------------------------------------------------------------
__global__ __launch_bounds__(256) void softmax_k(float* __restrict__ P)
{
    const long long row = blockIdx.x;
    const int s = (int)(row & (S_LEN - 1));
    float* p = P + row * S_LEN;
    const int tid = threadIdx.x;

    float v[8];
    float mx = -FLT_MAX;
#pragma unroll
    for (int i = 0; i < 8; i++) {
        const int t = tid + i * 256;
        v[i] = (t <= s) ? p[t] : -FLT_MAX;
        mx = fmaxf(mx, v[i]);
    }
    __shared__ float red[8];
    for (int o = 16; o; o >>= 1) mx = fmaxf(mx, __shfl_xor_sync(0xffffffffu, mx, o));
    if ((tid & 31) == 0) red[tid >> 5] = mx;
    __syncthreads();
    if (tid < 8) {
        float m2 = red[tid];
        for (int o = 4; o; o >>= 1) m2 = fmaxf(m2, __shfl_xor_sync(0xffu, m2, o));
        if (tid == 0) red[0] = m2;
    }
    __syncthreads();
    mx = red[0];
    __syncthreads();

    float sum = 0.f;
#pragma unroll
    for (int i = 0; i < 8; i++) {
        const int t = tid + i * 256;
        v[i] = (t <= s) ? __expf(v[i] - mx) : 0.f;
        sum += v[i];
    }
    for (int o = 16; o; o >>= 1) sum += __shfl_xor_sync(0xffffffffu, sum, o);
    if ((tid & 31) == 0) red[tid >> 5] = sum;
    __syncthreads();
    if (tid < 8) {
        float s2 = red[tid];
        for (int o = 4; o; o >>= 1) s2 += __shfl_xor_sync(0xffu, s2, o);
        if (tid == 0) red[0] = s2;
    }
    __syncthreads();
    const float inv = 1.f / red[0];
#pragma unroll
    for (int i = 0; i < 8; i++) p[tid + i * 256] = v[i] * inv;
}

// ---------------------------------------------------------------------------
extern "C" void kernel_launch(void* const* d_in, const int* in_sizes, int n_in,
                              void* d_out, int out_size)
{
    const float* hs    = (const float*)d_in[0];
    const float* cosb  = (const float*)d_in[1];
    const float* sinb  = (const float*)d_in[2];
    const float* wq_a  = (const float*)d_in[4];
    const float* qnw   = (const float*)d_in[5];
    const float* wq_b  = (const float*)d_in[6];
    const float* wkv_a = (const float*)d_in[7];
    const float* kvnw  = (const float*)d_in[8];
    const float* wkv_b = (const float*)d_in[9];
    const float* wo    = (const float*)d_in[10];

    float* outp = (float*)d_out;
    float* attn = outp + (long long)BATCH * S_LEN * 2048;

    float *qa, *q, *kvf, *kve, *qe, *ctx, *obuf, *wbT, *kvT;
    cudaGetSymbolAddress((void**)&qa,   g_qa);
    cudaGetSymbolAddress((void**)&q,    g_q);
    cudaGetSymbolAddress((void**)&kvf,  g_kvfull);
    cudaGetSymbolAddress((void**)&kve,  g_kv_ext);
    cudaGetSymbolAddress((void**)&qe,   g_q_ext);
    cudaGetSymbolAddress((void**)&ctx,  g_ctx);
    cudaGetSymbolAddress((void**)&obuf, g_out);
    cudaGetSymbolAddress((void**)&wbT,  g_wbT);
    cudaGetSymbolAddress((void**)&kvT,  g_kvT);

    const float scaling = 1.f / sqrtf(192.f);
    const long long SS  = (long long)S_LEN * S_LEN;

    // 1. qa = hs @ wq_a^T               (4096 x 768, K=2048)
    gemm_mma<false, false><<<dim3(6, 32, 1), 256>>>(
        4096, 768, 2048, hs, 2048, 0, 0, wq_a, 2048, 0, 0,
        qa, 768, 0, 0, 1, 1.f);
    // 2. rmsnorm(qa)
    rmsnorm_k<<<4096, 256>>>(qa, 768, qnw, qa, 768, 768);
    // 3. q = qa @ wq_b^T                (4096 x 3072, K=768)
    gemm_mma<false, false><<<dim3(24, 32, 1), 256>>>(
        4096, 3072, 768, qa, 768, 0, 0, wq_b, 768, 0, 0,
        q, 3072, 0, 0, 1, 1.f);
    // 4. kvf = hs @ wkv_a^T             (4096 x 576, K=2048)
    gemm_mma<false, false><<<dim3(5, 32, 1), 256>>>(
        4096, 576, 2048, hs, 2048, 0, 0, wkv_a, 2048, 0, 0,
        kvf, 576, 0, 0, 1, 1.f);
    // 5-7. rmsnorm + rope
    rmsnorm_k<<<4096, 256>>>(kvf, 576, kvnw, kve, 576, 512);
    rope_k_k<<<4096, 64>>>(kvf, cosb, sinb, kve);
    rope_q_k<<<dim3(4096, 16), 64>>>(q, cosb, sinb, qe);
    // 7b. wbT[h] (512x128) = wkv_b_h[:128,:]^T
    transpose_k<<<dim3(4, 16, 16), dim3(32, 8)>>>(
        wkv_b, 512, (long long)256 * 512, wbT, 128, (long long)512 * 128,
        512, 128);
    // 8. q_ext[:, :512] = q_nope @ wbT^T  (per (b,h): 2048x512, K=128)
    gemm_mma<false, false><<<dim3(4, 16, 32), 256>>>(
        2048, 512, 128,
        q, 3072, (long long)2048 * 3072, 192,
        wbT, 128, 0, (long long)512 * 128,
        qe, 576, (long long)16 * 2048 * 576, (long long)2048 * 576,
        16, 1.f);
    // 9. scores = scaling * q_ext @ kv_ext^T (causal) -> d_out attn region
    gemm_mma<true, false><<<dim3(16, 16, 32), 256>>>(
        2048, 2048, 576,
        qe, 576, (long long)16 * 2048 * 576, (long long)2048 * 576,
        kve, 576, (long long)2048 * 576, 0,
        attn, 2048, 16 * SS, SS,
        16, scaling);
    // 10. causal softmax (in place, writes zeros above diagonal)
    softmax_k<<<BATCH * NHEADS * S_LEN, 256>>>(attn);
    // 10b. kvT[b] (512x2048) = kv_lat^T
    transpose_k<<<dim3(64, 16, 2), dim3(32, 8)>>>(
        kve, 576, (long long)2048 * 576, kvT, 2048, (long long)512 * 2048,
        512, 2048);
    // 11. ctx = P @ kvT^T  (K-limit)    (2048x512, K=2048)
    gemm_mma<false, true><<<dim3(4, 16, 32), 256>>>(
        2048, 512, 2048,
        attn, 2048, 16 * SS, SS,
        kvT, 2048, (long long)512 * 2048, 0,
        ctx, 512, (long long)16 * 2048 * 512, (long long)2048 * 512,
        16, 1.f);
    // 12. out = ctx @ wkv_b_h[:,128:]^T (per (b,h): 2048x128, K=512)
    gemm_mma<false, false><<<dim3(1, 16, 32), 256>>>(
        2048, 128, 512,
        ctx, 512, (long long)16 * 2048 * 512, (long long)2048 * 512,
        wkv_b + 128 * 512, 512, 0, (long long)256 * 512,
        obuf, 2048, (long long)2048 * 2048, 128,
        16, 1.f);
    // 13. attn_output = out @ wo^T      (4096 x 2048, K=2048)
    gemm_mma<false, false><<<dim3(16, 32, 1), 256>>>(
        4096, 2048, 2048, obuf, 2048, 0, 0, wo, 2048, 0, 0,
        outp, 2048, 0, 0, 1, 1.f);
}